// round 2
// baseline (speedup 1.0000x reference)
#include <cuda_runtime.h>
#include <cstddef>

#define NN   50000
#define EE   800000
#define HDIM 128
#define GG   512
#define OUTD 64
#define BN_EPS 1e-5f

// ---------------- device scratch (no allocation allowed) ----------------
__device__ __align__(16) float g_bufX[NN * HDIM];   // layer output / current x
__device__ __align__(16) float g_bufA[NN * HDIM];   // aggregation buffer
__device__ __align__(16) float g_bufB[NN * HDIM];   // h1 (pre-BN) buffer
__device__ __align__(16) float g_pool[GG * HDIM];
__device__ __align__(16) float g_head[GG * HDIM];
__device__ float g_stats[2 * HDIM];                 // col sum / col sumsq
__device__ float g_scale[HDIM];
__device__ float g_shift[HDIM];

// ---------------- helpers ----------------
__device__ __forceinline__ void red_add_f4(float4* addr, float4 v) {
    asm volatile("red.global.add.v4.f32 [%0], {%1,%2,%3,%4};"
                 :: "l"(addr), "f"(v.x), "f"(v.y), "f"(v.z), "f"(v.w)
                 : "memory");
}

// packed fp32x2 FMA (PTX-only path; 2 FMAs per instruction on sm_103a)
#define FFMA2(d, a, b) \
    asm("fma.rn.f32x2 %0, %1, %2, %0;" : "+l"(d) : "l"(a), "l"(b))

__device__ __forceinline__ float2 u2f2(unsigned long long u) {
    float2 f;
    asm("mov.b64 {%0,%1}, %2;" : "=f"(f.x), "=f"(f.y) : "l"(u));
    return f;
}

// ---------------- kernels ----------------

// copy x -> agg (self term of GIN, eps=0) ; block 0 also zeroes the BN stats
__global__ void copy_init_kernel(const float4* __restrict__ src,
                                 float4* __restrict__ dst, int n4,
                                 float* __restrict__ stats) {
    int i = blockIdx.x * blockDim.x + threadIdx.x;
    if (blockIdx.x == 0 && threadIdx.x < 2 * HDIM) stats[threadIdx.x] = 0.f;
    if (i < n4) dst[i] = src[i];
}

// one warp per edge: 32 lanes x float4 = full 512B feature row
__global__ void scatter_edges_kernel(const float4* __restrict__ x,
                                     float4* __restrict__ agg,
                                     const int* __restrict__ src,
                                     const int* __restrict__ dst,
                                     int E) {
    int e = blockIdx.x * 8 + (threadIdx.x >> 5);
    if (e >= E) return;
    int lane = threadIdx.x & 31;
    int s = src[e];
    int d = dst[e];
    float4 v = x[(size_t)s * 32 + lane];
    red_add_f4(&agg[(size_t)d * 32 + lane], v);
}

// M x 128 @ 128 x 128 GEMM, fp32 with packed f32x2 FMA.
// Block tile: 128 rows x 128 cols, 256 threads, 8x8 per thread (cols as 4 pairs).
// PRE_BN : apply y = relu(a*scale[k]+shift[k]) to A elements on load
// POST_RELU : relu on output
// STATS : accumulate per-column sum / sumsq (incl. bias) into stats[256]
template <bool PRE_BN, bool POST_RELU, bool STATS>
__global__ void __launch_bounds__(256, 2)
gemm_k128(const float* __restrict__ A, const float* __restrict__ W,
          const float* __restrict__ bias, const float* __restrict__ bnscale,
          const float* __restrict__ bnshift, float* __restrict__ out,
          float* __restrict__ stats, int M) {
    __shared__ float2 As2[128][16];   // [row][k] value duplicated in both halves
    __shared__ float2 Ws2[16][64];    // [k][col-pair]
    __shared__ float  s_bias[128];
    __shared__ float  s_scale[128];
    __shared__ float  s_shift[128];

    const int tid = threadIdx.x;
    if (tid < 128) {
        s_bias[tid] = bias[tid];
        if (PRE_BN) { s_scale[tid] = bnscale[tid]; s_shift[tid] = bnshift[tid]; }
    }

    const int ty = tid >> 4;   // 0..15 (row group)
    const int tx = tid & 15;   // 0..15 (col group)
    const int base_row = blockIdx.x * 128;

    unsigned long long acc[8][4];
#pragma unroll
    for (int i = 0; i < 8; i++)
#pragma unroll
        for (int p = 0; p < 4; p++) acc[i][p] = 0ull;

    for (int kb = 0; kb < 128; kb += 16) {
        __syncthreads();
        // fill A tile (512 float4 loads over 256 threads)
#pragma unroll
        for (int t = 0; t < 2; t++) {
            int idx = tid + t * 256;          // 0..511
            int row = idx >> 2;               // 0..127
            int j   = idx & 3;                // float4 within the 16-k chunk
            int gr  = base_row + row;
            float4 v = make_float4(0.f, 0.f, 0.f, 0.f);
            if (gr < M)
                v = *(const float4*)(A + (size_t)gr * 128 + kb + 4 * j);
            if (PRE_BN) {
                int k = kb + 4 * j;
                v.x = fmaxf(fmaf(v.x, s_scale[k + 0], s_shift[k + 0]), 0.f);
                v.y = fmaxf(fmaf(v.y, s_scale[k + 1], s_shift[k + 1]), 0.f);
                v.z = fmaxf(fmaf(v.z, s_scale[k + 2], s_shift[k + 2]), 0.f);
                v.w = fmaxf(fmaf(v.w, s_scale[k + 3], s_shift[k + 3]), 0.f);
            }
            As2[row][4 * j + 0] = make_float2(v.x, v.x);
            As2[row][4 * j + 1] = make_float2(v.y, v.y);
            As2[row][4 * j + 2] = make_float2(v.z, v.z);
            As2[row][4 * j + 3] = make_float2(v.w, v.w);
        }
        // fill W tile: rows kb..kb+15 of W (each 128 floats)
#pragma unroll
        for (int t = 0; t < 2; t++) {
            int idx = tid + t * 256;          // 0..511
            int kk = idx >> 5;                // 0..15
            int c4 = idx & 31;                // float4 along columns
            float4 w = *(const float4*)(W + (size_t)(kb + kk) * 128 + 4 * c4);
            Ws2[kk][2 * c4 + 0] = make_float2(w.x, w.y);
            Ws2[kk][2 * c4 + 1] = make_float2(w.z, w.w);
        }
        __syncthreads();

        const unsigned long long* Asu = (const unsigned long long*)As2;
        const unsigned long long* Wsu = (const unsigned long long*)Ws2;
#pragma unroll
        for (int kk = 0; kk < 16; kk++) {
            unsigned long long a2[8], w2[4];
#pragma unroll
            for (int i = 0; i < 8; i++) a2[i] = Asu[(ty * 8 + i) * 16 + kk];
#pragma unroll
            for (int p = 0; p < 4; p++) w2[p] = Wsu[kk * 64 + tx + p * 16];
#pragma unroll
            for (int i = 0; i < 8; i++)
#pragma unroll
                for (int p = 0; p < 4; p++) FFMA2(acc[i][p], a2[i], w2[p]);
        }
    }

    // epilogue
    float2 csum[4], csq[4];
    if (STATS) {
#pragma unroll
        for (int p = 0; p < 4; p++) {
            csum[p] = make_float2(0.f, 0.f);
            csq[p]  = make_float2(0.f, 0.f);
        }
    }
#pragma unroll
    for (int i = 0; i < 8; i++) {
        int r = base_row + ty * 8 + i;
        if (r < M) {
#pragma unroll
            for (int p = 0; p < 4; p++) {
                int col = 2 * (tx + p * 16);
                float2 v = u2f2(acc[i][p]);
                v.x += s_bias[col];
                v.y += s_bias[col + 1];
                if (POST_RELU) { v.x = fmaxf(v.x, 0.f); v.y = fmaxf(v.y, 0.f); }
                *(float2*)(out + (size_t)r * 128 + col) = v;
                if (STATS) {
                    csum[p].x += v.x;        csum[p].y += v.y;
                    csq[p].x  += v.x * v.x;  csq[p].y  += v.y * v.y;
                }
            }
        }
    }

    if (STATS) {
        __syncthreads();                       // done reading As2
        float* ssum = (float*)&As2[0][0];      // 128 floats
        float* ssq  = ssum + 128;              // 128 floats
        ssum[tid] = 0.f;                       // 256 threads zero both arrays
        __syncthreads();
#pragma unroll
        for (int p = 0; p < 4; p++) {
            int col = 2 * (tx + p * 16);
            atomicAdd(&ssum[col],     csum[p].x);
            atomicAdd(&ssum[col + 1], csum[p].y);
            atomicAdd(&ssq[col],      csq[p].x);
            atomicAdd(&ssq[col + 1],  csq[p].y);
        }
        __syncthreads();
        if (tid < 128) {
            atomicAdd(&stats[tid],       ssum[tid]);
            atomicAdd(&stats[128 + tid], ssq[tid]);
        }
    }
}

__global__ void bn_finalize_kernel(const float* __restrict__ stats,
                                   const float* __restrict__ gamma,
                                   const float* __restrict__ beta,
                                   float* __restrict__ scale,
                                   float* __restrict__ shift, float invM) {
    int c = threadIdx.x;
    float mu   = stats[c] * invM;
    float var  = stats[128 + c] * invM - mu * mu;
    float rstd = rsqrtf(var + BN_EPS);
    float sc   = gamma[c] * rstd;
    scale[c] = sc;
    shift[c] = beta[c] - mu * sc;
}

__global__ void zero_pool_kernel(float4* __restrict__ pool) {
    int i = blockIdx.x * blockDim.x + threadIdx.x;   // 64*256 = 16384 float4
    pool[i] = make_float4(0.f, 0.f, 0.f, 0.f);
}

// one warp per node
__global__ void pool_scatter_kernel(const float4* __restrict__ x,
                                    float4* __restrict__ pool,
                                    const int* __restrict__ batch,
                                    int N) {
    int n = blockIdx.x * 8 + (threadIdx.x >> 5);
    if (n >= N) return;
    int lane = threadIdx.x & 31;
    int g = batch[n];
    float4 v = x[(size_t)n * 32 + lane];
    red_add_f4(&pool[(size_t)g * 32 + lane], v);
}

// [G,128] @ [128,64] + bias -> out (no relu)
__global__ void head2_kernel(const float* __restrict__ Hh,
                             const float* __restrict__ W,
                             const float* __restrict__ b,
                             float* __restrict__ out) {
    __shared__ float row[128];
    int g = blockIdx.x;
    int c = threadIdx.x;            // 0..63
    row[c]      = Hh[(size_t)g * 128 + c];
    row[c + 64] = Hh[(size_t)g * 128 + 64 + c];
    __syncthreads();
    float acc = b[c];
#pragma unroll 8
    for (int k = 0; k < 128; k++) acc = fmaf(row[k], W[k * 64 + c], acc);
    out[(size_t)g * 64 + c] = acc;
}

// ---------------- launcher ----------------
extern "C" void kernel_launch(void* const* d_in, const int* in_sizes, int n_in,
                              void* d_out, int out_size) {
    const float* x    = (const float*)d_in[0];
    const float* cW1  = (const float*)d_in[1];
    const float* cb1  = (const float*)d_in[2];
    const float* cgam = (const float*)d_in[3];
    const float* cbet = (const float*)d_in[4];
    const float* cW2  = (const float*)d_in[5];
    const float* cb2  = (const float*)d_in[6];
    const float* hW1  = (const float*)d_in[7];
    const float* hb1  = (const float*)d_in[8];
    const float* hW2  = (const float*)d_in[9];
    const float* hb2  = (const float*)d_in[10];
    // JAX default config has x64 disabled: int64 requests come through as int32.
    const int* ei    = (const int*)d_in[11];   // [2, E] int32
    const int* batch = (const int*)d_in[12];   // [N]    int32
    float* out = (float*)d_out;

    float *bufX, *bufA, *bufB, *pool, *head, *stats, *scale, *shift;
    cudaGetSymbolAddress((void**)&bufX,  g_bufX);
    cudaGetSymbolAddress((void**)&bufA,  g_bufA);
    cudaGetSymbolAddress((void**)&bufB,  g_bufB);
    cudaGetSymbolAddress((void**)&pool,  g_pool);
    cudaGetSymbolAddress((void**)&head,  g_head);
    cudaGetSymbolAddress((void**)&stats, g_stats);
    cudaGetSymbolAddress((void**)&scale, g_scale);
    cudaGetSymbolAddress((void**)&shift, g_shift);

    const int n4 = NN * 32;                    // float4 count per node buffer
    const int gemm_blocks = (NN + 127) / 128;  // 391

    for (int l = 0; l < 3; l++) {
        const float* in = (l == 0) ? x : bufX;
        copy_init_kernel<<<(n4 + 255) / 256, 256>>>(
            (const float4*)in, (float4*)bufA, n4, stats);
        scatter_edges_kernel<<<(EE + 7) / 8, 256>>>(
            (const float4*)in, (float4*)bufA, ei, ei + EE, EE);
        gemm_k128<false, false, true><<<gemm_blocks, 256>>>(
            bufA, cW1 + l * HDIM * HDIM, cb1 + l * HDIM,
            nullptr, nullptr, bufB, stats, NN);
        bn_finalize_kernel<<<1, 128>>>(stats, cgam + l * HDIM, cbet + l * HDIM,
                                       scale, shift, 1.0f / NN);
        gemm_k128<true, true, false><<<gemm_blocks, 256>>>(
            bufB, cW2 + l * HDIM * HDIM, cb2 + l * HDIM,
            scale, shift, bufX, nullptr, NN);
    }

    zero_pool_kernel<<<64, 256>>>((float4*)pool);
    pool_scatter_kernel<<<(NN + 7) / 8, 256>>>(
        (const float4*)bufX, (float4*)pool, batch, NN);
    gemm_k128<false, true, false><<<(GG + 127) / 128, 256>>>(
        pool, hW1, hb1, nullptr, nullptr, head, nullptr, GG);
    head2_kernel<<<GG, 64>>>(head, hW2, hb2, out);
}

// round 3
// speedup vs baseline: 1.1454x; 1.1454x over previous
#include <cuda_runtime.h>
#include <cstddef>

#define NN   50000
#define EE   800000
#define HDIM 128
#define GG   512
#define OUTD 64
#define BN_EPS 1e-5f

// ---------------- device scratch (no allocation allowed) ----------------
__device__ __align__(16) float g_bufX[NN * HDIM];   // layer output / current x
__device__ __align__(16) float g_bufA[NN * HDIM];   // aggregation buffer
__device__ __align__(16) float g_bufB[NN * HDIM];   // h1 (pre-BN) buffer
__device__ __align__(16) float g_pool[GG * HDIM];
__device__ __align__(16) float g_head[GG * HDIM];
__device__ float g_stats[2 * HDIM];                 // col sum / col sumsq
// CSR scratch
__device__ int g_deg[NN];
__device__ int g_rowptr[NN + 1];
__device__ int g_cursor[NN];
__device__ int g_csr[EE];

// ---------------- helpers ----------------
__device__ __forceinline__ void red_add_f4(float4* addr, float4 v) {
    asm volatile("red.global.add.v4.f32 [%0], {%1,%2,%3,%4};"
                 :: "l"(addr), "f"(v.x), "f"(v.y), "f"(v.z), "f"(v.w)
                 : "memory");
}

#define FFMA2(d, a, b) \
    asm("fma.rn.f32x2 %0, %1, %2, %0;" : "+l"(d) : "l"(a), "l"(b))

__device__ __forceinline__ float2 u2f2(unsigned long long u) {
    float2 f;
    asm("mov.b64 {%0,%1}, %2;" : "=f"(f.x), "=f"(f.y) : "l"(u));
    return f;
}

// ---------------- CSR build kernels ----------------
__global__ void zero_deg_kernel(int* __restrict__ deg) {
    int i = blockIdx.x * blockDim.x + threadIdx.x;
    if (i < NN) deg[i] = 0;
}

__global__ void hist_kernel(const int* __restrict__ dst, int* __restrict__ deg) {
    int e = blockIdx.x * blockDim.x + threadIdx.x;
    if (e < EE) atomicAdd(&deg[dst[e]], 1);
}

// single-block exclusive scan of deg -> rowptr (and cursor copy)
__global__ void scan_kernel(const int* __restrict__ deg,
                            int* __restrict__ rowptr,
                            int* __restrict__ cursor) {
    __shared__ int ssum[1024];
    const int T = 1024, CH = (NN + T - 1) / T;   // 49
    int t = threadIdx.x;
    int begin = t * CH;
    int end = begin + CH; if (end > NN) end = NN;
    int s = 0;
    for (int i = begin; i < end && i >= 0; i++) s += deg[i];
    ssum[t] = s;
    __syncthreads();
    for (int off = 1; off < T; off <<= 1) {
        int v = (t >= off) ? ssum[t - off] : 0;
        __syncthreads();
        ssum[t] += v;
        __syncthreads();
    }
    int run = (t == 0) ? 0 : ssum[t - 1];
    for (int i = begin; i < end; i++) {
        rowptr[i] = run;
        cursor[i] = run;
        run += deg[i];
    }
    if (t == T - 1) rowptr[NN] = ssum[T - 1];
}

__global__ void fill_kernel(const int* __restrict__ src,
                            const int* __restrict__ dst,
                            int* __restrict__ cursor,
                            int* __restrict__ csr) {
    int e = blockIdx.x * blockDim.x + threadIdx.x;
    if (e >= EE) return;
    int pos = atomicAdd(&cursor[dst[e]], 1);
    csr[pos] = src[e];
}

// ---------------- aggregation: warp per node, gather over CSR ----------------
// agg[n] = x[n] + sum_{s in neighbors(n)} x[s]; block 0 also zeroes BN stats
__global__ void gather_kernel(const float4* __restrict__ x,
                              float4* __restrict__ agg,
                              const int* __restrict__ rowptr,
                              const int* __restrict__ csr,
                              float* __restrict__ stats) {
    if (blockIdx.x == 0 && threadIdx.x < 2 * HDIM) stats[threadIdx.x] = 0.f;
    int n = blockIdx.x * 8 + (threadIdx.x >> 5);
    if (n >= NN) return;
    int lane = threadIdx.x & 31;
    int b = rowptr[n], e = rowptr[n + 1];
    float4 a0 = x[(size_t)n * 32 + lane];
    float4 a1 = make_float4(0.f, 0.f, 0.f, 0.f);
    float4 a2 = make_float4(0.f, 0.f, 0.f, 0.f);
    float4 a3 = make_float4(0.f, 0.f, 0.f, 0.f);
    int i = b;
    for (; i + 4 <= e; i += 4) {
        int s0 = csr[i], s1 = csr[i + 1], s2 = csr[i + 2], s3 = csr[i + 3];
        float4 v0 = x[(size_t)s0 * 32 + lane];
        float4 v1 = x[(size_t)s1 * 32 + lane];
        float4 v2 = x[(size_t)s2 * 32 + lane];
        float4 v3 = x[(size_t)s3 * 32 + lane];
        a0.x += v0.x; a0.y += v0.y; a0.z += v0.z; a0.w += v0.w;
        a1.x += v1.x; a1.y += v1.y; a1.z += v1.z; a1.w += v1.w;
        a2.x += v2.x; a2.y += v2.y; a2.z += v2.z; a2.w += v2.w;
        a3.x += v3.x; a3.y += v3.y; a3.z += v3.z; a3.w += v3.w;
    }
    for (; i < e; i++) {
        int s = csr[i];
        float4 v = x[(size_t)s * 32 + lane];
        a0.x += v.x; a0.y += v.y; a0.z += v.z; a0.w += v.w;
    }
    a0.x += a1.x + a2.x + a3.x;
    a0.y += a1.y + a2.y + a3.y;
    a0.z += a1.z + a2.z + a3.z;
    a0.w += a1.w + a2.w + a3.w;
    agg[(size_t)n * 32 + lane] = a0;
}

// ---------------- GEMM ----------------
// M x 128 @ 128 x 128, fp32 packed f32x2 FMA.
// PRE_BN : A' = relu(A*scale[k]+shift[k]) with scale/shift derived in-block
//          from stats/gamma/beta (BN finalize folded in)
// POST_RELU : relu on output
// STATS : accumulate per-column sum / sumsq (incl. bias) into stats[256]
template <bool PRE_BN, bool POST_RELU, bool STATS>
__global__ void __launch_bounds__(256, 2)
gemm_k128(const float* __restrict__ A, const float* __restrict__ W,
          const float* __restrict__ bias, const float* __restrict__ gamma,
          const float* __restrict__ beta, float* __restrict__ out,
          float* __restrict__ stats, int M, float invM) {
    __shared__ float2 As2[128][16];   // [row][k] duplicated in both halves
    __shared__ float2 Ws2[16][64];    // [k][col-pair]
    __shared__ float  s_bias[128];
    __shared__ float  s_scale[128];
    __shared__ float  s_shift[128];

    const int tid = threadIdx.x;
    if (tid < 128) {
        s_bias[tid] = bias[tid];
        if (PRE_BN) {
            float mu   = stats[tid] * invM;
            float var  = stats[128 + tid] * invM - mu * mu;
            float rstd = rsqrtf(var + BN_EPS);
            float sc   = gamma[tid] * rstd;
            s_scale[tid] = sc;
            s_shift[tid] = beta[tid] - mu * sc;
        }
    }

    const int ty = tid >> 4;
    const int tx = tid & 15;
    const int base_row = blockIdx.x * 128;

    unsigned long long acc[8][4];
#pragma unroll
    for (int i = 0; i < 8; i++)
#pragma unroll
        for (int p = 0; p < 4; p++) acc[i][p] = 0ull;

    for (int kb = 0; kb < 128; kb += 16) {
        __syncthreads();
#pragma unroll
        for (int t = 0; t < 2; t++) {
            int idx = tid + t * 256;
            int row = idx >> 2;
            int j   = idx & 3;
            int gr  = base_row + row;
            float4 v = make_float4(0.f, 0.f, 0.f, 0.f);
            if (gr < M)
                v = *(const float4*)(A + (size_t)gr * 128 + kb + 4 * j);
            if (PRE_BN) {
                int k = kb + 4 * j;
                v.x = fmaxf(fmaf(v.x, s_scale[k + 0], s_shift[k + 0]), 0.f);
                v.y = fmaxf(fmaf(v.y, s_scale[k + 1], s_shift[k + 1]), 0.f);
                v.z = fmaxf(fmaf(v.z, s_scale[k + 2], s_shift[k + 2]), 0.f);
                v.w = fmaxf(fmaf(v.w, s_scale[k + 3], s_shift[k + 3]), 0.f);
            }
            As2[row][4 * j + 0] = make_float2(v.x, v.x);
            As2[row][4 * j + 1] = make_float2(v.y, v.y);
            As2[row][4 * j + 2] = make_float2(v.z, v.z);
            As2[row][4 * j + 3] = make_float2(v.w, v.w);
        }
#pragma unroll
        for (int t = 0; t < 2; t++) {
            int idx = tid + t * 256;
            int kk = idx >> 5;
            int c4 = idx & 31;
            float4 w = *(const float4*)(W + (size_t)(kb + kk) * 128 + 4 * c4);
            Ws2[kk][2 * c4 + 0] = make_float2(w.x, w.y);
            Ws2[kk][2 * c4 + 1] = make_float2(w.z, w.w);
        }
        __syncthreads();

        const unsigned long long* Asu = (const unsigned long long*)As2;
        const unsigned long long* Wsu = (const unsigned long long*)Ws2;
#pragma unroll
        for (int kk = 0; kk < 16; kk++) {
            unsigned long long a2[8], w2[4];
#pragma unroll
            for (int i = 0; i < 8; i++) a2[i] = Asu[(ty * 8 + i) * 16 + kk];
#pragma unroll
            for (int p = 0; p < 4; p++) w2[p] = Wsu[kk * 64 + tx + p * 16];
#pragma unroll
            for (int i = 0; i < 8; i++)
#pragma unroll
                for (int p = 0; p < 4; p++) FFMA2(acc[i][p], a2[i], w2[p]);
        }
    }

    float2 csum[4], csq[4];
    if (STATS) {
#pragma unroll
        for (int p = 0; p < 4; p++) {
            csum[p] = make_float2(0.f, 0.f);
            csq[p]  = make_float2(0.f, 0.f);
        }
    }
#pragma unroll
    for (int i = 0; i < 8; i++) {
        int r = base_row + ty * 8 + i;
        if (r < M) {
#pragma unroll
            for (int p = 0; p < 4; p++) {
                int col = 2 * (tx + p * 16);
                float2 v = u2f2(acc[i][p]);
                v.x += s_bias[col];
                v.y += s_bias[col + 1];
                if (POST_RELU) { v.x = fmaxf(v.x, 0.f); v.y = fmaxf(v.y, 0.f); }
                *(float2*)(out + (size_t)r * 128 + col) = v;
                if (STATS) {
                    csum[p].x += v.x;        csum[p].y += v.y;
                    csq[p].x  += v.x * v.x;  csq[p].y  += v.y * v.y;
                }
            }
        }
    }

    if (STATS) {
        __syncthreads();
        float* ssum = (float*)&As2[0][0];
        float* ssq  = ssum + 128;
        ssum[tid] = 0.f;                 // 256 threads zero both arrays
        __syncthreads();
#pragma unroll
        for (int p = 0; p < 4; p++) {
            int col = 2 * (tx + p * 16);
            atomicAdd(&ssum[col],     csum[p].x);
            atomicAdd(&ssum[col + 1], csum[p].y);
            atomicAdd(&ssq[col],      csq[p].x);
            atomicAdd(&ssq[col + 1],  csq[p].y);
        }
        __syncthreads();
        if (tid < 128) {
            atomicAdd(&stats[tid],       ssum[tid]);
            atomicAdd(&stats[128 + tid], ssq[tid]);
        }
    }
}

__global__ void zero_pool_kernel(float4* __restrict__ pool) {
    int i = blockIdx.x * blockDim.x + threadIdx.x;
    pool[i] = make_float4(0.f, 0.f, 0.f, 0.f);
}

__global__ void pool_scatter_kernel(const float4* __restrict__ x,
                                    float4* __restrict__ pool,
                                    const int* __restrict__ batch,
                                    int N) {
    int n = blockIdx.x * 8 + (threadIdx.x >> 5);
    if (n >= N) return;
    int lane = threadIdx.x & 31;
    int g = batch[n];
    float4 v = x[(size_t)n * 32 + lane];
    red_add_f4(&pool[(size_t)g * 32 + lane], v);
}

__global__ void head2_kernel(const float* __restrict__ Hh,
                             const float* __restrict__ W,
                             const float* __restrict__ b,
                             float* __restrict__ out) {
    __shared__ float row[128];
    int g = blockIdx.x;
    int c = threadIdx.x;
    row[c]      = Hh[(size_t)g * 128 + c];
    row[c + 64] = Hh[(size_t)g * 128 + 64 + c];
    __syncthreads();
    float acc = b[c];
#pragma unroll 8
    for (int k = 0; k < 128; k++) acc = fmaf(row[k], W[k * 64 + c], acc);
    out[(size_t)g * 64 + c] = acc;
}

// ---------------- launcher ----------------
extern "C" void kernel_launch(void* const* d_in, const int* in_sizes, int n_in,
                              void* d_out, int out_size) {
    const float* x    = (const float*)d_in[0];
    const float* cW1  = (const float*)d_in[1];
    const float* cb1  = (const float*)d_in[2];
    const float* cgam = (const float*)d_in[3];
    const float* cbet = (const float*)d_in[4];
    const float* cW2  = (const float*)d_in[5];
    const float* cb2  = (const float*)d_in[6];
    const float* hW1  = (const float*)d_in[7];
    const float* hb1  = (const float*)d_in[8];
    const float* hW2  = (const float*)d_in[9];
    const float* hb2  = (const float*)d_in[10];
    const int* ei    = (const int*)d_in[11];   // [2, E] int32
    const int* batch = (const int*)d_in[12];   // [N]    int32
    float* out = (float*)d_out;

    float *bufX, *bufA, *bufB, *pool, *head, *stats;
    int *deg, *rowptr, *cursor, *csr;
    cudaGetSymbolAddress((void**)&bufX,   g_bufX);
    cudaGetSymbolAddress((void**)&bufA,   g_bufA);
    cudaGetSymbolAddress((void**)&bufB,   g_bufB);
    cudaGetSymbolAddress((void**)&pool,   g_pool);
    cudaGetSymbolAddress((void**)&head,   g_head);
    cudaGetSymbolAddress((void**)&stats,  g_stats);
    cudaGetSymbolAddress((void**)&deg,    g_deg);
    cudaGetSymbolAddress((void**)&rowptr, g_rowptr);
    cudaGetSymbolAddress((void**)&cursor, g_cursor);
    cudaGetSymbolAddress((void**)&csr,    g_csr);

    const int* e_src = ei;
    const int* e_dst = ei + EE;
    const int gemm_blocks = (NN + 127) / 128;  // 391

    // CSR build (once per call, reused by all 3 layers)
    zero_deg_kernel<<<(NN + 255) / 256, 256>>>(deg);
    hist_kernel<<<(EE + 255) / 256, 256>>>(e_dst, deg);
    scan_kernel<<<1, 1024>>>(deg, rowptr, cursor);
    fill_kernel<<<(EE + 255) / 256, 256>>>(e_src, e_dst, cursor, csr);

    for (int l = 0; l < 3; l++) {
        const float* in = (l == 0) ? x : bufX;
        gather_kernel<<<(NN + 7) / 8, 256>>>(
            (const float4*)in, (float4*)bufA, rowptr, csr, stats);
        gemm_k128<false, false, true><<<gemm_blocks, 256>>>(
            bufA, cW1 + l * HDIM * HDIM, cb1 + l * HDIM,
            nullptr, nullptr, bufB, stats, NN, 0.f);
        gemm_k128<true, true, false><<<gemm_blocks, 256>>>(
            bufB, cW2 + l * HDIM * HDIM, cb2 + l * HDIM,
            cgam + l * HDIM, cbet + l * HDIM, bufX, stats, NN, 1.0f / NN);
    }

    zero_pool_kernel<<<64, 256>>>((float4*)pool);
    pool_scatter_kernel<<<(NN + 7) / 8, 256>>>(
        (const float4*)bufX, (float4*)pool, batch, NN);
    gemm_k128<false, true, false><<<(GG + 127) / 128, 256>>>(
        pool, hW1, hb1, nullptr, nullptr, head, nullptr, GG, 0.f);
    head2_kernel<<<GG, 64>>>(head, hW2, hb2, out);
}

// round 4
// speedup vs baseline: 1.1795x; 1.0298x over previous
#include <cuda_runtime.h>
#include <cstddef>

#define NN   50000
#define EE   800000
#define HDIM 128
#define GG   512
#define OUTD 64
#define BN_EPS 1e-5f

// ---------------- device scratch (no allocation allowed) ----------------
__device__ __align__(16) float g_bufX[NN * HDIM];
__device__ __align__(16) float g_bufA[NN * HDIM];
__device__ __align__(16) float g_bufB[NN * HDIM];
__device__ __align__(16) float g_pool[GG * HDIM];
__device__ __align__(16) float g_head[GG * HDIM];
__device__ __align__(16) float g_stats[2 * HDIM];
__device__ __align__(16) float g_scaleK[HDIM];
__device__ __align__(16) float g_shiftK[HDIM];
// CSR scratch
__device__ int g_deg[NN];
__device__ int g_rowptr[NN + 1];
__device__ int g_cursor[NN];
__device__ int g_csr[EE];

// ---------------- helpers ----------------
__device__ __forceinline__ void red_add_f4(float4* addr, float4 v) {
    asm volatile("red.global.add.v4.f32 [%0], {%1,%2,%3,%4};"
                 :: "l"(addr), "f"(v.x), "f"(v.y), "f"(v.z), "f"(v.w)
                 : "memory");
}

#define FFMA2(d, a, b) \
    asm("fma.rn.f32x2 %0, %1, %2, %0;" : "+l"(d) : "l"(a), "l"(b))

__device__ __forceinline__ float2 u2f2(unsigned long long u) {
    float2 f;
    asm("mov.b64 {%0,%1}, %2;" : "=f"(f.x), "=f"(f.y) : "l"(u));
    return f;
}

__device__ __forceinline__ void cp_async16(void* smem_dst, const void* gsrc,
                                           int src_bytes) {
    unsigned d = (unsigned)__cvta_generic_to_shared(smem_dst);
    asm volatile("cp.async.cg.shared.global [%0], [%1], 16, %2;"
                 :: "r"(d), "l"(gsrc), "r"(src_bytes));
}
__device__ __forceinline__ void cp_async16(void* smem_dst, const void* gsrc) {
    unsigned d = (unsigned)__cvta_generic_to_shared(smem_dst);
    asm volatile("cp.async.cg.shared.global [%0], [%1], 16;"
                 :: "r"(d), "l"(gsrc));
}
#define CP_COMMIT()  asm volatile("cp.async.commit_group;")
#define CP_WAIT0()   asm volatile("cp.async.wait_group 0;")

// ---------------- CSR build kernels ----------------
__global__ void zero_deg_kernel(int* __restrict__ deg) {
    int i = blockIdx.x * blockDim.x + threadIdx.x;
    if (i < NN) deg[i] = 0;
}

__global__ void hist_kernel(const int* __restrict__ dst, int* __restrict__ deg) {
    int e = blockIdx.x * blockDim.x + threadIdx.x;
    if (e < EE) atomicAdd(&deg[dst[e]], 1);
}

__global__ void scan_kernel(const int* __restrict__ deg,
                            int* __restrict__ rowptr,
                            int* __restrict__ cursor) {
    __shared__ int ssum[1024];
    const int T = 1024, CH = (NN + T - 1) / T;
    int t = threadIdx.x;
    int begin = t * CH;
    int end = begin + CH; if (end > NN) end = NN;
    int s = 0;
    for (int i = begin; i < end && i >= 0; i++) s += deg[i];
    ssum[t] = s;
    __syncthreads();
    for (int off = 1; off < T; off <<= 1) {
        int v = (t >= off) ? ssum[t - off] : 0;
        __syncthreads();
        ssum[t] += v;
        __syncthreads();
    }
    int run = (t == 0) ? 0 : ssum[t - 1];
    for (int i = begin; i < end; i++) {
        rowptr[i] = run;
        cursor[i] = run;
        run += deg[i];
    }
    if (t == T - 1) rowptr[NN] = ssum[T - 1];
}

__global__ void fill_kernel(const int* __restrict__ src,
                            const int* __restrict__ dst,
                            int* __restrict__ cursor,
                            int* __restrict__ csr) {
    int e = blockIdx.x * blockDim.x + threadIdx.x;
    if (e >= EE) return;
    int pos = atomicAdd(&cursor[dst[e]], 1);
    csr[pos] = src[e];
}

// ---------------- aggregation: warp per node, gather over CSR ----------------
__global__ void gather_kernel(const float4* __restrict__ x,
                              float4* __restrict__ agg,
                              const int* __restrict__ rowptr,
                              const int* __restrict__ csr,
                              float* __restrict__ stats) {
    if (blockIdx.x == 0 && threadIdx.x < 2 * HDIM) stats[threadIdx.x] = 0.f;
    int n = blockIdx.x * 8 + (threadIdx.x >> 5);
    if (n >= NN) return;
    int lane = threadIdx.x & 31;
    int b = rowptr[n], e = rowptr[n + 1];
    float4 a0 = x[(size_t)n * 32 + lane];
    float4 a1 = make_float4(0.f, 0.f, 0.f, 0.f);
    float4 a2 = make_float4(0.f, 0.f, 0.f, 0.f);
    float4 a3 = make_float4(0.f, 0.f, 0.f, 0.f);
    int i = b;
    for (; i + 4 <= e; i += 4) {
        int s0 = csr[i], s1 = csr[i + 1], s2 = csr[i + 2], s3 = csr[i + 3];
        float4 v0 = x[(size_t)s0 * 32 + lane];
        float4 v1 = x[(size_t)s1 * 32 + lane];
        float4 v2 = x[(size_t)s2 * 32 + lane];
        float4 v3 = x[(size_t)s3 * 32 + lane];
        a0.x += v0.x; a0.y += v0.y; a0.z += v0.z; a0.w += v0.w;
        a1.x += v1.x; a1.y += v1.y; a1.z += v1.z; a1.w += v1.w;
        a2.x += v2.x; a2.y += v2.y; a2.z += v2.z; a2.w += v2.w;
        a3.x += v3.x; a3.y += v3.y; a3.z += v3.z; a3.w += v3.w;
    }
    for (; i < e; i++) {
        int s = csr[i];
        float4 v = x[(size_t)s * 32 + lane];
        a0.x += v.x; a0.y += v.y; a0.z += v.z; a0.w += v.w;
    }
    a0.x += a1.x + a2.x + a3.x;
    a0.y += a1.y + a2.y + a3.y;
    a0.z += a1.z + a2.z + a3.z;
    a0.w += a1.w + a2.w + a3.w;
    agg[(size_t)n * 32 + lane] = a0;
}

// ---------------- GEMM: cp.async double-buffered, conflict-free smem --------
// M x 128 @ 128 x 128, fp32 packed f32x2 FMA.
// PRE_BN : A' = relu(A*scaleK[k]+shiftK[k]) applied in the transform pass
// POST_RELU : relu on output
// STATS : per-column sum/sumsq of output accumulated to stats[256]
template <bool PRE_BN, bool POST_RELU, bool STATS>
__global__ void __launch_bounds__(256, 2)
gemm_k128(const float* __restrict__ A, const float* __restrict__ W,
          const float* __restrict__ bias, const float* __restrict__ scaleK,
          const float* __restrict__ shiftK, float* __restrict__ out,
          float* __restrict__ stats, int M) {
    __shared__ float  stageA[2][128][16];   // 16 KB raw A tiles
    __shared__ float2 Ws[2][16][64];        // 16 KB raw W tiles (pair layout)
    __shared__ float2 As2[16][128];         // 16 KB duplicated, kk-major

    const int tid = threadIdx.x;
    const int ty = tid >> 4;
    const int tx = tid & 15;
    const int base_row = blockIdx.x * 128;

    unsigned long long acc[8][4];
#pragma unroll
    for (int i = 0; i < 8; i++)
#pragma unroll
        for (int p = 0; p < 4; p++) acc[i][p] = 0ull;

    // ---- issue tile kb into buffer buf ----
    auto issue_tile = [&](int buf, int kb) {
#pragma unroll
        for (int t = 0; t < 2; t++) {
            int idx = tid + t * 256;        // 512 chunks: A 128 rows x 4
            int row = idx >> 2, j = idx & 3;
            int gr  = base_row + row;
            int cgr = gr < M ? gr : 0;
            cp_async16(&stageA[buf][row][4 * j],
                       A + (size_t)cgr * 128 + kb + 4 * j,
                       gr < M ? 16 : 0);
        }
#pragma unroll
        for (int t = 0; t < 2; t++) {
            int idx = tid + t * 256;        // 512 chunks: W 16 rows x 32
            int kk = idx >> 5, c = idx & 31;
            cp_async16(&Ws[buf][kk][2 * c],
                       W + (size_t)(kb + kk) * 128 + 4 * c);
        }
        CP_COMMIT();
    };

    issue_tile(0, 0);

    for (int kb8 = 0; kb8 < 8; kb8++) {
        const int buf = kb8 & 1;
        CP_WAIT0();
        __syncthreads();                    // tile kb8 visible; prev compute done
        if (kb8 < 7) issue_tile(buf ^ 1, (kb8 + 1) * 16);

        // transform: stageA[buf] -> As2 (duplicate, optional BN+ReLU)
#pragma unroll
        for (int t = 0; t < 2; t++) {
            int idx = tid + t * 256;
            int row = idx >> 2, j = idx & 3;
            float4 v = *(const float4*)&stageA[buf][row][4 * j];
            if (PRE_BN) {
                int k = kb8 * 16 + 4 * j;
                float4 sc = *(const float4*)(scaleK + k);
                float4 sh = *(const float4*)(shiftK + k);
                v.x = fmaxf(fmaf(v.x, sc.x, sh.x), 0.f);
                v.y = fmaxf(fmaf(v.y, sc.y, sh.y), 0.f);
                v.z = fmaxf(fmaf(v.z, sc.z, sh.z), 0.f);
                v.w = fmaxf(fmaf(v.w, sc.w, sh.w), 0.f);
            }
            As2[4 * j + 0][row] = make_float2(v.x, v.x);
            As2[4 * j + 1][row] = make_float2(v.y, v.y);
            As2[4 * j + 2][row] = make_float2(v.z, v.z);
            As2[4 * j + 3][row] = make_float2(v.w, v.w);
        }
        __syncthreads();

        const unsigned long long* Asu = (const unsigned long long*)As2;
        const unsigned long long* Wsu = (const unsigned long long*)Ws[buf];
#pragma unroll
        for (int kk = 0; kk < 16; kk++) {
            unsigned long long a2[8], w2[4];
#pragma unroll
            for (int i = 0; i < 8; i++) a2[i] = Asu[kk * 128 + ty * 8 + i];
#pragma unroll
            for (int p = 0; p < 4; p++) w2[p] = Wsu[kk * 64 + tx + p * 16];
#pragma unroll
            for (int i = 0; i < 8; i++)
#pragma unroll
                for (int p = 0; p < 4; p++) FFMA2(acc[i][p], a2[i], w2[p]);
        }
    }

    // ---- epilogue ----
    float2 b2[4];
#pragma unroll
    for (int p = 0; p < 4; p++)
        b2[p] = *(const float2*)(bias + 2 * (tx + p * 16));

    float2 csum[4], csq[4];
    if (STATS) {
#pragma unroll
        for (int p = 0; p < 4; p++) {
            csum[p] = make_float2(0.f, 0.f);
            csq[p]  = make_float2(0.f, 0.f);
        }
    }
#pragma unroll
    for (int i = 0; i < 8; i++) {
        int r = base_row + ty * 8 + i;
        if (r < M) {
#pragma unroll
            for (int p = 0; p < 4; p++) {
                int col = 2 * (tx + p * 16);
                float2 v = u2f2(acc[i][p]);
                v.x += b2[p].x;
                v.y += b2[p].y;
                if (POST_RELU) { v.x = fmaxf(v.x, 0.f); v.y = fmaxf(v.y, 0.f); }
                *(float2*)(out + (size_t)r * 128 + col) = v;
                if (STATS) {
                    csum[p].x += v.x;        csum[p].y += v.y;
                    csq[p].x  += v.x * v.x;  csq[p].y  += v.y * v.y;
                }
            }
        }
    }

    if (STATS) {
        __syncthreads();
        float* ssum = (float*)&As2[0][0];
        float* ssq  = ssum + 128;
        ssum[tid] = 0.f;                 // 256 threads zero both arrays
        __syncthreads();
#pragma unroll
        for (int p = 0; p < 4; p++) {
            int col = 2 * (tx + p * 16);
            atomicAdd(&ssum[col],     csum[p].x);
            atomicAdd(&ssum[col + 1], csum[p].y);
            atomicAdd(&ssq[col],      csq[p].x);
            atomicAdd(&ssq[col + 1],  csq[p].y);
        }
        __syncthreads();
        if (tid < 128) {
            atomicAdd(&stats[tid],       ssum[tid]);
            atomicAdd(&stats[128 + tid], ssq[tid]);
        }
    }
}

__global__ void bn_finalize_kernel(const float* __restrict__ stats,
                                   const float* __restrict__ gamma,
                                   const float* __restrict__ beta,
                                   float* __restrict__ scaleK,
                                   float* __restrict__ shiftK, float invM) {
    int c = threadIdx.x;
    float mu   = stats[c] * invM;
    float var  = stats[128 + c] * invM - mu * mu;
    float rstd = rsqrtf(var + BN_EPS);
    float sc   = gamma[c] * rstd;
    scaleK[c] = sc;
    shiftK[c] = beta[c] - mu * sc;
}

__global__ void zero_pool_kernel(float4* __restrict__ pool) {
    int i = blockIdx.x * blockDim.x + threadIdx.x;
    pool[i] = make_float4(0.f, 0.f, 0.f, 0.f);
}

__global__ void pool_scatter_kernel(const float4* __restrict__ x,
                                    float4* __restrict__ pool,
                                    const int* __restrict__ batch,
                                    int N) {
    int n = blockIdx.x * 8 + (threadIdx.x >> 5);
    if (n >= N) return;
    int lane = threadIdx.x & 31;
    int g = batch[n];
    float4 v = x[(size_t)n * 32 + lane];
    red_add_f4(&pool[(size_t)g * 32 + lane], v);
}

__global__ void head2_kernel(const float* __restrict__ Hh,
                             const float* __restrict__ W,
                             const float* __restrict__ b,
                             float* __restrict__ out) {
    __shared__ float row[128];
    int g = blockIdx.x;
    int c = threadIdx.x;
    row[c]      = Hh[(size_t)g * 128 + c];
    row[c + 64] = Hh[(size_t)g * 128 + 64 + c];
    __syncthreads();
    float acc = b[c];
#pragma unroll 8
    for (int k = 0; k < 128; k++) acc = fmaf(row[k], W[k * 64 + c], acc);
    out[(size_t)g * 64 + c] = acc;
}

// ---------------- launcher ----------------
extern "C" void kernel_launch(void* const* d_in, const int* in_sizes, int n_in,
                              void* d_out, int out_size) {
    const float* x    = (const float*)d_in[0];
    const float* cW1  = (const float*)d_in[1];
    const float* cb1  = (const float*)d_in[2];
    const float* cgam = (const float*)d_in[3];
    const float* cbet = (const float*)d_in[4];
    const float* cW2  = (const float*)d_in[5];
    const float* cb2  = (const float*)d_in[6];
    const float* hW1  = (const float*)d_in[7];
    const float* hb1  = (const float*)d_in[8];
    const float* hW2  = (const float*)d_in[9];
    const float* hb2  = (const float*)d_in[10];
    const int* ei    = (const int*)d_in[11];   // [2, E] int32
    const int* batch = (const int*)d_in[12];   // [N]    int32
    float* out = (float*)d_out;

    float *bufX, *bufA, *bufB, *pool, *head, *stats, *scaleK, *shiftK;
    int *deg, *rowptr, *cursor, *csr;
    cudaGetSymbolAddress((void**)&bufX,   g_bufX);
    cudaGetSymbolAddress((void**)&bufA,   g_bufA);
    cudaGetSymbolAddress((void**)&bufB,   g_bufB);
    cudaGetSymbolAddress((void**)&pool,   g_pool);
    cudaGetSymbolAddress((void**)&head,   g_head);
    cudaGetSymbolAddress((void**)&stats,  g_stats);
    cudaGetSymbolAddress((void**)&scaleK, g_scaleK);
    cudaGetSymbolAddress((void**)&shiftK, g_shiftK);
    cudaGetSymbolAddress((void**)&deg,    g_deg);
    cudaGetSymbolAddress((void**)&rowptr, g_rowptr);
    cudaGetSymbolAddress((void**)&cursor, g_cursor);
    cudaGetSymbolAddress((void**)&csr,    g_csr);

    const int* e_src = ei;
    const int* e_dst = ei + EE;
    const int gemm_blocks = (NN + 127) / 128;  // 391

    // CSR build (reused by all 3 layers)
    zero_deg_kernel<<<(NN + 255) / 256, 256>>>(deg);
    hist_kernel<<<(EE + 255) / 256, 256>>>(e_dst, deg);
    scan_kernel<<<1, 1024>>>(deg, rowptr, cursor);
    fill_kernel<<<(EE + 255) / 256, 256>>>(e_src, e_dst, cursor, csr);

    for (int l = 0; l < 3; l++) {
        const float* in = (l == 0) ? x : bufX;
        gather_kernel<<<(NN + 7) / 8, 256>>>(
            (const float4*)in, (float4*)bufA, rowptr, csr, stats);
        gemm_k128<false, false, true><<<gemm_blocks, 256>>>(
            bufA, cW1 + l * HDIM * HDIM, cb1 + l * HDIM,
            nullptr, nullptr, bufB, stats, NN);
        bn_finalize_kernel<<<1, 128>>>(stats, cgam + l * HDIM, cbet + l * HDIM,
                                       scaleK, shiftK, 1.0f / NN);
        gemm_k128<true, true, false><<<gemm_blocks, 256>>>(
            bufB, cW2 + l * HDIM * HDIM, cb2 + l * HDIM,
            scaleK, shiftK, bufX, nullptr, NN);
    }

    zero_pool_kernel<<<64, 256>>>((float4*)pool);
    pool_scatter_kernel<<<(NN + 7) / 8, 256>>>(
        (const float4*)bufX, (float4*)pool, batch, NN);
    gemm_k128<false, true, false><<<(GG + 127) / 128, 256>>>(
        pool, hW1, hb1, nullptr, nullptr, head, nullptr, GG);
    head2_kernel<<<GG, 64>>>(head, hW2, hb2, out);
}